// round 3
// baseline (speedup 1.0000x reference)
#include <cuda_runtime.h>
#include <math.h>

#define Bb 4
#define Tt 128
#define Ss 512
#define Hh 512

typedef unsigned long long ull;

// Scratch (device globals; allocation-free per harness rules)
__device__ float g_pq[Bb * Tt * Hh];     // query @ W_s
__device__ float g_pe[Bb * Ss * Hh];     // encoder @ W_h
__device__ float g_score[Bb * Tt * Ss];  // scores -> alignment (in place)
__device__ float g_ctx[Bb * Tt * Hh];    // alignment @ encoder

__device__ __forceinline__ float tanh_fast(float x) {
    float y;
    asm("tanh.approx.f32 %0, %1;" : "=f"(y) : "f"(x));
    return y;
}

// Packed fp32x2 FMA (sm_100+ full-rate fp32 path; ptxas never auto-fuses this)
__device__ __forceinline__ void ffma2(ull& d, ull a, ull b) {
    asm("fma.rn.f32x2 %0, %1, %2, %0;" : "+l"(d) : "l"(a), "l"(b));
}
__device__ __forceinline__ ull splat2(float x) {
    ull r;
    asm("mov.b64 %0, {%1, %1};" : "=l"(r) : "f"(x));
    return r;
}
__device__ __forceinline__ void unpack2(ull p, float& lo, float& hi) {
    asm("mov.b64 {%0, %1}, %2;" : "=f"(lo), "=f"(hi) : "l"(p));
}

// ---------------------------------------------------------------------------
// SGEMM v3 (FFMA2): C[M,N] = concat_K(A0,A1) @ W, row-major, optional tanh
// epilogue, batched via blockIdx.z. Tile BM x BN x 32, micro-tile 4(M) x TN(N)
// per thread, THREADS = (BM/4)*(BN/TN). Accumulators packed as f32x2 pairs
// along N; W operands read from smem directly as pairs (LDS.128 -> 2 f32x2),
// A scalars splatted once per kk (ALU pipe). Double-buffered smem + register
// prefetch. Requires: M%BM==0, N%BN==0, K%32==0, Ksplit%32==0.
// ---------------------------------------------------------------------------
template <int BM, int BN, int TN, bool DO_TANH>
__global__ __launch_bounds__((BM / 4) * (BN / TN)) void sgemm3(
    const float* __restrict__ A0, const float* __restrict__ A1,
    const float* __restrict__ W, float* __restrict__ C,
    int N, int K, int Ksplit, int lda0, int lda1,
    long batchA0, long batchW, long batchC)
{
    constexpr int BK = 32;
    constexpr int THREADS = (BM / 4) * (BN / TN);
    constexpr int NP = TN / 2;                       // f32x2 pairs per thread (N)
    constexpr int A_IT = (BM * BK) / (4 * THREADS);  // float4 loads for A tile
    constexpr int W_IT = (BK * BN) / (4 * THREADS);  // float4 loads for W tile

    __shared__ float As[2][BK][BM];   // transposed [k][m]
    __shared__ float Ws[2][BK][BN];   // [k][n]

    const int b = blockIdx.z;
    const float* A0b = A0 + (long)b * batchA0;
    const float* Wb  = W  + (long)b * batchW;
    float*       Cb  = C  + (long)b * batchC;

    const int row0 = blockIdx.y * BM;
    const int col0 = blockIdx.x * BN;
    const int tid = threadIdx.x;
    const int txn = tid % (BN / TN);
    const int tym = tid / (BN / TN);

    float4 aF[A_IT];
    float4 wF[W_IT];
    ull acc[4][NP];
    #pragma unroll
    for (int i = 0; i < 4; i++)
        #pragma unroll
        for (int j = 0; j < NP; j++) acc[i][j] = 0ULL;

    auto loadChunk = [&](int k0) {
        #pragma unroll
        for (int i = 0; i < A_IT; i++) {
            int idx = tid + i * THREADS;
            int r  = idx / (BK / 4);
            int kc = (idx % (BK / 4)) * 4;
            int gk = k0 + kc;
            const float* src = (gk < Ksplit)
                ? A0b + (long)(row0 + r) * lda0 + gk
                : A1  + (long)(row0 + r) * lda1 + (gk - Ksplit);
            aF[i] = *(const float4*)src;
        }
        #pragma unroll
        for (int i = 0; i < W_IT; i++) {
            int idx = tid + i * THREADS;
            int r = idx / (BN / 4);
            int c = (idx % (BN / 4)) * 4;
            wF[i] = *(const float4*)(Wb + (long)(k0 + r) * N + col0 + c);
        }
    };
    auto storeChunk = [&](int buf) {
        #pragma unroll
        for (int i = 0; i < A_IT; i++) {
            int idx = tid + i * THREADS;
            int r  = idx / (BK / 4);
            int kc = (idx % (BK / 4)) * 4;
            As[buf][kc + 0][r] = aF[i].x;
            As[buf][kc + 1][r] = aF[i].y;
            As[buf][kc + 2][r] = aF[i].z;
            As[buf][kc + 3][r] = aF[i].w;
        }
        #pragma unroll
        for (int i = 0; i < W_IT; i++) {
            int idx = tid + i * THREADS;
            int r = idx / (BN / 4);
            int c = (idx % (BN / 4)) * 4;
            *(float4*)&Ws[buf][r][c] = wF[i];
        }
    };
    auto compute = [&](int buf) {
        #pragma unroll
        for (int kk = 0; kk < BK; kk++) {
            float4 a4 = *(const float4*)&As[buf][kk][tym * 4];
            ull asp[4] = {splat2(a4.x), splat2(a4.y), splat2(a4.z), splat2(a4.w)};
            ull wp[NP];
            #pragma unroll
            for (int q = 0; q < NP / 2; q++) {
                ulonglong2 w2 = *(const ulonglong2*)&Ws[buf][kk][txn * TN + q * 4];
                wp[q * 2 + 0] = w2.x;
                wp[q * 2 + 1] = w2.y;
            }
            #pragma unroll
            for (int i = 0; i < 4; i++)
                #pragma unroll
                for (int j = 0; j < NP; j++)
                    ffma2(acc[i][j], asp[i], wp[j]);
        }
    };

    loadChunk(0);
    storeChunk(0);
    __syncthreads();

    int buf = 0;
    for (int k0 = BK; k0 < K; k0 += BK) {
        loadChunk(k0);          // LDG for next chunk in flight during compute
        compute(buf);
        storeChunk(buf ^ 1);
        __syncthreads();
        buf ^= 1;
    }
    compute(buf);

    #pragma unroll
    for (int i = 0; i < 4; i++) {
        int r = row0 + tym * 4 + i;
        #pragma unroll
        for (int q = 0; q < NP / 2; q++) {
            float4 o;
            unpack2(acc[i][q * 2 + 0], o.x, o.y);
            unpack2(acc[i][q * 2 + 1], o.z, o.w);
            if (DO_TANH) {
                o.x = tanhf(o.x); o.y = tanhf(o.y);
                o.z = tanhf(o.z); o.w = tanhf(o.w);
            }
            *(float4*)(Cb + (long)r * N + col0 + txn * TN + q * 4) = o;
        }
    }
}

// ---------------------------------------------------------------------------
// Score kernel: score[b,t,s] = sum_h v[h] * tanh(pq[b,t,h] + pe[b,s,h])
// Block tile: 16 t x 64 s, h chunked by 128 through smem. 256 threads,
// each owns a 2(t) x 2(s) register tile. MUFU.TANH bound by design.
// ---------------------------------------------------------------------------
__global__ __launch_bounds__(256) void score_kernel(const float* __restrict__ v)
{
    __shared__ float pe_s[64][132];
    __shared__ float pq_s[16][132];
    __shared__ float v_s[128];

    const int b  = blockIdx.z;
    const int t0 = blockIdx.y * 16;
    const int s0 = blockIdx.x * 64;
    const int tid = threadIdx.x;
    const int tx = tid & 31;   // s lane
    const int ty = tid >> 5;   // t pair (0..7)

    float acc00 = 0.f, acc01 = 0.f, acc10 = 0.f, acc11 = 0.f;

    for (int h0 = 0; h0 < Hh; h0 += 128) {
        for (int i = tid; i < 64 * 32; i += 256) {
            int r = i >> 5, c = (i & 31) * 4;
            float4 x = *(const float4*)(g_pe + (long)(b * Ss + s0 + r) * Hh + h0 + c);
            *(float4*)&pe_s[r][c] = x;
        }
        for (int i = tid; i < 16 * 32; i += 256) {
            int r = i >> 5, c = (i & 31) * 4;
            float4 x = *(const float4*)(g_pq + (long)(b * Tt + t0 + r) * Hh + h0 + c);
            *(float4*)&pq_s[r][c] = x;
        }
        if (tid < 32)
            *(float4*)&v_s[tid * 4] = *(const float4*)(v + h0 + tid * 4);
        __syncthreads();

        #pragma unroll 8
        for (int hh = 0; hh < 128; hh += 4) {
            float4 vv = *(const float4*)&v_s[hh];
            float4 a0 = *(const float4*)&pq_s[ty * 2 + 0][hh];
            float4 a1 = *(const float4*)&pq_s[ty * 2 + 1][hh];
            float4 e0 = *(const float4*)&pe_s[tx][hh];
            float4 e1 = *(const float4*)&pe_s[tx + 32][hh];

            acc00 += vv.x * tanh_fast(a0.x + e0.x) + vv.y * tanh_fast(a0.y + e0.y)
                   + vv.z * tanh_fast(a0.z + e0.z) + vv.w * tanh_fast(a0.w + e0.w);
            acc01 += vv.x * tanh_fast(a0.x + e1.x) + vv.y * tanh_fast(a0.y + e1.y)
                   + vv.z * tanh_fast(a0.z + e1.z) + vv.w * tanh_fast(a0.w + e1.w);
            acc10 += vv.x * tanh_fast(a1.x + e0.x) + vv.y * tanh_fast(a1.y + e0.y)
                   + vv.z * tanh_fast(a1.z + e0.z) + vv.w * tanh_fast(a1.w + e0.w);
            acc11 += vv.x * tanh_fast(a1.x + e1.x) + vv.y * tanh_fast(a1.y + e1.y)
                   + vv.z * tanh_fast(a1.z + e1.z) + vv.w * tanh_fast(a1.w + e1.w);
        }
        __syncthreads();
    }

    const int t_a = t0 + ty * 2, t_b = t_a + 1;
    g_score[(long)(b * Tt + t_a) * Ss + s0 + tx]      = acc00;
    g_score[(long)(b * Tt + t_a) * Ss + s0 + tx + 32] = acc01;
    g_score[(long)(b * Tt + t_b) * Ss + s0 + tx]      = acc10;
    g_score[(long)(b * Tt + t_b) * Ss + s0 + tx + 32] = acc11;
}

// ---------------------------------------------------------------------------
// Masked softmax over S, in place on g_score. One block (128 threads) per
// (b,t) row of 512 floats; each thread owns one float4.
// ---------------------------------------------------------------------------
__global__ __launch_bounds__(128) void softmax_kernel(const int* __restrict__ src_len)
{
    const int row = blockIdx.x;          // b*T + t
    const int b = row / Tt;
    const int len = src_len[b];
    const int tid = threadIdx.x;
    float* sp = g_score + (long)row * Ss;

    __shared__ float redm[4];
    __shared__ float reds[4];

    const int sbase = tid * 4;
    float4 x4 = *(const float4*)(sp + sbase);
    float xv[4] = {x4.x, x4.y, x4.z, x4.w};
    #pragma unroll
    for (int i = 0; i < 4; i++)
        if (sbase + i >= len) xv[i] = -3.0e38f;

    float m = fmaxf(fmaxf(xv[0], xv[1]), fmaxf(xv[2], xv[3]));
    #pragma unroll
    for (int off = 16; off; off >>= 1)
        m = fmaxf(m, __shfl_xor_sync(0xffffffffu, m, off));
    if ((tid & 31) == 0) redm[tid >> 5] = m;
    __syncthreads();
    m = fmaxf(fmaxf(redm[0], redm[1]), fmaxf(redm[2], redm[3]));

    float e[4];
    float ssum = 0.f;
    #pragma unroll
    for (int i = 0; i < 4; i++) {
        e[i] = (sbase + i < len) ? expf(xv[i] - m) : 0.f;
        ssum += e[i];
    }
    #pragma unroll
    for (int off = 16; off; off >>= 1)
        ssum += __shfl_xor_sync(0xffffffffu, ssum, off);
    if ((tid & 31) == 0) reds[tid >> 5] = ssum;
    __syncthreads();
    ssum = reds[0] + reds[1] + reds[2] + reds[3];

    const float inv = 1.0f / ssum;
    float4 o;
    o.x = e[0] * inv; o.y = e[1] * inv; o.z = e[2] * inv; o.w = e[3] * inv;
    *(float4*)(sp + sbase) = o;
}

// ---------------------------------------------------------------------------
// Launch
// ---------------------------------------------------------------------------
extern "C" void kernel_launch(void* const* d_in, const int* in_sizes, int n_in,
                              void* d_out, int out_size)
{
    const float* query = (const float*)d_in[0];  // (B,T,H)
    const float* enc   = (const float*)d_in[1];  // (B,S,H)
    const int*   slen  = (const int*)d_in[2];    // (B,)
    const float* W_h   = (const float*)d_in[3];  // (H,H)
    const float* W_s   = (const float*)d_in[4];  // (H,H)
    const float* v     = (const float*)d_in[5];  // (H,)
    const float* W_out = (const float*)d_in[6];  // (2H,H)
    float* out = (float*)d_out;                  // (B,T,H)

    float *pq, *pe, *score, *ctx;
    cudaGetSymbolAddress((void**)&pq,    g_pq);
    cudaGetSymbolAddress((void**)&pe,    g_pe);
    cudaGetSymbolAddress((void**)&score, g_score);
    cudaGetSymbolAddress((void**)&ctx,   g_ctx);

    // 1) pe = encoder @ W_h  (M=2048, N=512, K=512) : 256 blocks, 4x8 micro
    sgemm3<64, 64, 8, false><<<dim3(8, 32, 1), 128>>>(enc, enc, W_h, pe,
        Hh, Hh, Hh, Hh, Hh, 0L, 0L, 0L);

    // 2) pq = query @ W_s    (M=512) : 128 blocks, 4x4 micro
    sgemm3<32, 64, 4, false><<<dim3(8, 16, 1), 128>>>(query, query, W_s, pq,
        Hh, Hh, Hh, Hh, Hh, 0L, 0L, 0L);

    // 3) scores
    score_kernel<<<dim3(Ss / 64, Tt / 16, Bb), 256>>>(v);

    // 4) masked softmax (in place -> alignment)
    softmax_kernel<<<Bb * Tt, 128>>>(slen);

    // 5) context[b] = alignment[b] @ encoder[b]  (M=128, K=512) : 128 blocks
    sgemm3<32, 64, 4, false><<<dim3(8, 4, Bb), 128>>>(score, score, enc, ctx,
        Hh, Ss, Ss, Ss, Ss, (long)Tt * Ss, (long)Ss * Hh, (long)Tt * Hh);

    // 6) out = tanh(concat(ctx, query) @ W_out)  (M=512, K=1024) : 128 blocks
    sgemm3<32, 64, 4, true><<<dim3(8, 16, 1), 128>>>(ctx, query, W_out, out,
        Hh, 2 * Hh, Hh, Hh, Hh, 0L, 0L, 0L);
}